// round 6
// baseline (speedup 1.0000x reference)
#include <cuda_runtime.h>
#include <math.h>
#include <stdint.h>

// Problem constants
#define NB 2
#define SSEQ 4096
#define NV 50257
#define NH 1024
#define MASKID 50256
#define NROWS (NB * SSEQ)      // 8192
#define NCTA 148               // one CTA per SM, single wave
#define TPB 128
#define ROWB 4096              // bytes per row (NH * 4)
#define NSTG 16                // smem FIFO stages (64 KB)
#define DSTORE 6               // max S2G bulk_groups in flight
#define PFILL (NSTG - DSTORE)  // refill distance = 10
#define MAXR 64                // >= max rows per CTA (56)

// ---- minimal PTX wrappers ----
__device__ __forceinline__ uint32_t smem_u32(const void* p) {
    uint32_t a;
    asm("{ .reg .u64 t; cvta.to.shared.u64 t, %1; cvt.u32.u64 %0, t; }"
        : "=r"(a) : "l"(p));
    return a;
}
#define MBAR_INIT(a, c) \
    asm volatile("mbarrier.init.shared.b64 [%0], %1;" :: "r"(a), "r"(c) : "memory")
#define MBAR_EXPECT(a, b) \
    asm volatile("mbarrier.arrive.expect_tx.shared.b64 _, [%0], %1;" :: "r"(a), "r"(b) : "memory")
#define MBAR_WAIT(a, ph) \
    asm volatile("{\n\t.reg .pred P;\n\tWL_%=:\n\t" \
                 "mbarrier.try_wait.parity.shared.b64 P, [%0], %1;\n\t" \
                 "@!P bra WL_%=;\n\t}" :: "r"(a), "r"(ph) : "memory")
#define BULK_G2S(dst, src, sz, mbar) \
    asm volatile("cp.async.bulk.shared::cta.global.mbarrier::complete_tx::bytes " \
                 "[%0], [%1], %2, [%3];" \
                 :: "r"(dst), "l"(src), "r"(sz), "r"(mbar) : "memory")
#define BULK_S2G(dst, src, sz) \
    asm volatile("cp.async.bulk.global.shared::cta.bulk_group [%0], [%1], %2;" \
                 :: "l"(dst), "r"(src), "r"(sz) : "memory")
#define BULK_COMMIT() asm volatile("cp.async.bulk.commit_group;" ::: "memory")
#define BULK_WAITG(n) asm volatile("cp.async.bulk.wait_group %0;" :: "n"(n) : "memory")

__device__ __forceinline__ void ins3(float v, int i,
                                     float& v0, int& i0,
                                     float& v1, int& i1,
                                     float& v2, int& i2)
{
    if (v > v0 || (v == v0 && i < i0)) {
        v2 = v1; i2 = i1; v1 = v0; i1 = i0; v0 = v; i0 = i;
    } else if (v > v1 || (v == v1 && i < i1)) {
        v2 = v1; i2 = i1; v1 = v; i1 = i;
    } else if (v > v2 || (v == v2 && i < i2)) {
        v2 = v; i2 = i;
    }
}

// Rare path: one warp computes top-3 + entropy + interpolated output for a mask row.
__device__ void heavy_row(int row, int lane,
                          const float* __restrict__ probs,
                          const float* __restrict__ embed,
                          const float* __restrict__ p_os,
                          const float* __restrict__ p_oa,
                          const float* __restrict__ p_ob,
                          float* __restrict__ out)
{
    const float* p = probs + (size_t)row * NV;

    float v0 = -1e30f, v1 = -1e30f, v2 = -1e30f;
    int   i0 = 0x7fffffff, i1 = 0x7fffffff, i2 = 0x7fffffff;
    float ent = 0.0f;

    for (int i = lane; i < NV; i += 32) {
        float v = p[i];
        if (v > 0.0f) ent -= v * __logf(v);
        ins3(v, i, v0, i0, v1, i1, v2, i2);
    }
#pragma unroll
    for (int off = 16; off > 0; off >>= 1) {
        ent += __shfl_xor_sync(0xffffffffu, ent, off);
        float ov0 = __shfl_xor_sync(0xffffffffu, v0, off);
        float ov1 = __shfl_xor_sync(0xffffffffu, v1, off);
        float ov2 = __shfl_xor_sync(0xffffffffu, v2, off);
        int   oi0 = __shfl_xor_sync(0xffffffffu, i0, off);
        int   oi1 = __shfl_xor_sync(0xffffffffu, i1, off);
        int   oi2 = __shfl_xor_sync(0xffffffffu, i2, off);
        ins3(ov0, oi0, v0, i0, v1, i1, v2, i2);
        ins3(ov1, oi1, v0, i0, v1, i1, v2, i2);
        ins3(ov2, oi2, v0, i0, v1, i1, v2, i2);
    }

    float ssum = v0 + v1 + v2 + 1e-10f;
    float w0 = v0 / ssum, w1 = v1 / ssum, w2 = v2 / ssum;

    float os = p_os[0], oa = p_oa[0], ob = p_ob[0];
    float sp_oa = (oa > 20.0f) ? oa : log1pf(expf(oa));
    float sp_ob = (ob > 20.0f) ? ob : log1pf(expf(ob));
    float sig_os = 1.0f / (1.0f + expf(-os));
    float arg = sp_oa * (sp_ob - ent);
    float lam = sig_os * (1.0f / (1.0f + expf(-arg)));

    const float4* e0 = (const float4*)(embed + (size_t)i0 * NH);
    const float4* e1 = (const float4*)(embed + (size_t)i1 * NH);
    const float4* e2 = (const float4*)(embed + (size_t)i2 * NH);
    const float4* er = (const float4*)(embed + (size_t)MASKID * NH);
    float4* orow = (float4*)(out + (size_t)row * NH);

#pragma unroll
    for (int j = 0; j < 8; ++j) {
        int c = lane + 32 * j;
        float4 a = e0[c], b = e1[c], cc = e2[c], r = er[c];
        float4 o;
        o.x = (1.0f - lam) * r.x + lam * (w0 * a.x + w1 * b.x + w2 * cc.x);
        o.y = (1.0f - lam) * r.y + lam * (w0 * a.y + w1 * b.y + w2 * cc.y);
        o.z = (1.0f - lam) * r.z + lam * (w0 * a.z + w1 * b.z + w2 * cc.z);
        o.w = (1.0f - lam) * r.w + lam * (w0 * a.w + w1 * b.w + w2 * cc.w);
        orow[c] = o;
    }
}

extern __shared__ char dsm[];

// dynamic smem layout
#define OFF_MBAR (NSTG * ROWB)            // 65536
#define OFF_TOK  (OFF_MBAR + NSTG * 8)    // +128
#define OFF_LIST (OFF_TOK + MAXR * 4)
#define SMEM_TOTAL (OFF_LIST + MAXR * 4)

__global__ __launch_bounds__(TPB)
void softmask_tma(const void* __restrict__ x_t_raw,
                  const float* __restrict__ probs,
                  const float* __restrict__ embed,
                  const float* __restrict__ p_os,
                  const float* __restrict__ p_oa,
                  const float* __restrict__ p_ob,
                  float* __restrict__ out)
{
    const int tid  = threadIdx.x;
    const int bid  = blockIdx.x;
    const int warp = tid >> 5;
    const int lane = tid & 31;

    const uint32_t sb = smem_u32(dsm);
    int* stoks = (int*)(dsm + OFF_TOK);
    int* slist = (int*)(dsm + OFF_LIST);

    // rows assigned to this CTA: r = bid + k*NCTA
    const int nrows = (NROWS - bid + NCTA - 1) / NCTA;   // 55 or 56

    // ---- dtype-width detection (int64 vs int32) + token preload ----
    const int* xi = (const int*)x_t_raw;
    const bool is64 = (xi[1] == 0) & (xi[3] == 0) & (xi[5] == 0) & (xi[7] == 0);
    if (tid < nrows) {
        int row = bid + tid * NCTA;
        stoks[tid] = is64 ? (int)((const long long*)x_t_raw)[row] : xi[row];
    }
    if (tid == 0) {
#pragma unroll
        for (int s = 0; s < NSTG; ++s) MBAR_INIT(sb + OFF_MBAR + 8 * s, 1);
    }
    __syncthreads();

    // ---- warp 1: handle (rare) mask rows concurrently with the DMA driver ----
    if (warp == 1) {
        for (int k = 0; k < nrows; ++k) {
            if (stoks[k] == MASKID)
                heavy_row(bid + k * NCTA, lane, probs, embed, p_os, p_oa, p_ob, out);
        }
        return;
    }
    if (tid != 0) return;

    // ---- driver thread: bulk-copy pipeline for non-mask rows ----
    int n = 0;
    for (int k = 0; k < nrows; ++k)
        if (stoks[k] != MASKID) slist[n++] = k;

    // prefill
    const int npf = (PFILL < n) ? PFILL : n;
    for (int j = 0; j < npf; ++j) {
        int k = slist[j];
        uint64_t src = (uint64_t)(const char*)(embed + (size_t)stoks[k] * NH);
        uint32_t mb = sb + OFF_MBAR + 8 * j;
        MBAR_EXPECT(mb, ROWB);
        BULK_G2S(sb + j * ROWB, src, ROWB, mb);
    }

    // steady state
    for (int i = 0; i < n; ++i) {
        const int st = i & (NSTG - 1);
        const int ph = (i >> 4) & 1;              // NSTG = 16
        MBAR_WAIT(sb + OFF_MBAR + 8 * st, ph);    // G2S(i) complete

        int k = slist[i];
        uint64_t dst = (uint64_t)(char*)(out + (size_t)(bid + k * NCTA) * NH);
        BULK_S2G(dst, sb + st * ROWB, ROWB);
        BULK_COMMIT();

        const int j = i + PFILL;                  // refill
        if (j < n) {
            if (j >= NSTG) BULK_WAITG(DSTORE);    // stage (j % NSTG) store drained
            int kj = slist[j];
            int stj = j & (NSTG - 1);
            uint64_t src = (uint64_t)(const char*)(embed + (size_t)stoks[kj] * NH);
            uint32_t mb = sb + OFF_MBAR + 8 * stj;
            MBAR_EXPECT(mb, ROWB);
            BULK_G2S(sb + stj * ROWB, src, ROWB, mb);
        }
    }
    BULK_WAITG(0);   // all stores complete before kernel retire
}

extern "C" void kernel_launch(void* const* d_in, const int* in_sizes, int n_in,
                              void* d_out, int out_size)
{
    (void)in_sizes; (void)n_in; (void)out_size;
    const void*  x_t   = d_in[0];
    const float* probs = (const float*)d_in[1];
    const float* embed = (const float*)d_in[2];
    const float* om_s  = (const float*)d_in[3];
    const float* om_a  = (const float*)d_in[4];
    const float* om_b  = (const float*)d_in[5];
    float* out = (float*)d_out;

    cudaFuncSetAttribute(softmask_tma,
                         cudaFuncAttributeMaxDynamicSharedMemorySize, SMEM_TOTAL);
    softmask_tma<<<NCTA, TPB, SMEM_TOTAL>>>(x_t, probs, embed,
                                            om_s, om_a, om_b, out);
}

// round 7
// speedup vs baseline: 1.4006x; 1.4006x over previous
#include <cuda_runtime.h>
#include <math.h>
#include <stdint.h>

// Problem constants
#define NB 2
#define SSEQ 4096
#define NV 50257
#define NH 1024
#define MASKID 50256
#define NROWS (NB * SSEQ)      // 8192
#define NCTA 148               // one CTA per SM
#define TPB 128
#define ROWB 4096              // bytes per row (NH * 4)
#define NSTG 48                // one private stage per driver thread (192 KB)
#define MAXR 64                // >= max rows per CTA (56)

// ---- minimal PTX wrappers ----
__device__ __forceinline__ uint32_t smem_u32(const void* p) {
    uint32_t a;
    asm("{ .reg .u64 t; cvta.to.shared.u64 t, %1; cvt.u32.u64 %0, t; }"
        : "=r"(a) : "l"(p));
    return a;
}
#define MBAR_INIT(a, c) \
    asm volatile("mbarrier.init.shared.b64 [%0], %1;" :: "r"(a), "r"(c) : "memory")
#define MBAR_EXPECT(a, b) \
    asm volatile("mbarrier.arrive.expect_tx.shared.b64 _, [%0], %1;" :: "r"(a), "r"(b) : "memory")
#define MBAR_WAIT(a, ph) \
    asm volatile("{\n\t.reg .pred P;\n\tWL_%=:\n\t" \
                 "mbarrier.try_wait.parity.shared.b64 P, [%0], %1;\n\t" \
                 "@!P bra WL_%=;\n\t}" :: "r"(a), "r"(ph) : "memory")
#define BULK_G2S(dst, src, sz, mbar) \
    asm volatile("cp.async.bulk.shared::cta.global.mbarrier::complete_tx::bytes " \
                 "[%0], [%1], %2, [%3];" \
                 :: "r"(dst), "l"(src), "r"(sz), "r"(mbar) : "memory")
#define BULK_S2G(dst, src, sz) \
    asm volatile("cp.async.bulk.global.shared::cta.bulk_group [%0], [%1], %2;" \
                 :: "l"(dst), "r"(src), "r"(sz) : "memory")
#define BULK_COMMIT() asm volatile("cp.async.bulk.commit_group;" ::: "memory")
#define BULK_WAITG0() asm volatile("cp.async.bulk.wait_group 0;" ::: "memory")

__device__ __forceinline__ void ins3(float v, int i,
                                     float& v0, int& i0,
                                     float& v1, int& i1,
                                     float& v2, int& i2)
{
    if (v > v0 || (v == v0 && i < i0)) {
        v2 = v1; i2 = i1; v1 = v0; i1 = i0; v0 = v; i0 = i;
    } else if (v > v1 || (v == v1 && i < i1)) {
        v2 = v1; i2 = i1; v1 = v; i1 = i;
    } else if (v > v2 || (v == v2 && i < i2)) {
        v2 = v; i2 = i;
    }
}

extern __shared__ char dsm[];

// dynamic smem layout
#define OFF_MBAR (NSTG * ROWB)                 // 196608
#define OFF_TOK  (OFF_MBAR + NSTG * 8)         // +384
#define OFF_MLST (OFF_TOK + MAXR * 4)          // mask-row list
#define OFF_MCNT (OFF_MLST + MAXR * 4)
#define OFF_RED  (OFF_MCNT + 16)               // heavy-path reduction scratch
#define SMEM_TOTAL (OFF_RED + 256)

// Block-cooperative heavy path for a (rare) mask row. All TPB threads participate.
__device__ void heavy_row_block(int row, int tid,
                                const float* __restrict__ probs,
                                const float* __restrict__ embed,
                                const float* __restrict__ p_os,
                                const float* __restrict__ p_oa,
                                const float* __restrict__ p_ob,
                                float* __restrict__ out)
{
    const int lane = tid & 31;
    const int warp = tid >> 5;                  // 0..3
    float* rv  = (float*)(dsm + OFF_RED);       // [12] warp top-3 values
    int*   ri  = (int*)(dsm + OFF_RED + 48);    // [12] warp top-3 indices
    float* re  = (float*)(dsm + OFF_RED + 96);  // [4] warp entropies
    float* rb  = (float*)(dsm + OFF_RED + 112); // [4] lam, w0, w1, w2
    int*   rbi = (int*)(dsm + OFF_RED + 128);   // [3] global top-3 indices

    const float* p = probs + (size_t)row * NV;

    float v0 = -1e30f, v1 = -1e30f, v2 = -1e30f;
    int   i0 = 0x7fffffff, i1 = 0x7fffffff, i2 = 0x7fffffff;
    float ent = 0.0f;

    for (int i = tid; i < NV; i += TPB) {
        float v = p[i];
        if (v > 0.0f) ent -= v * __logf(v);
        ins3(v, i, v0, i0, v1, i1, v2, i2);
    }
#pragma unroll
    for (int off = 16; off > 0; off >>= 1) {
        ent += __shfl_xor_sync(0xffffffffu, ent, off);
        float ov0 = __shfl_xor_sync(0xffffffffu, v0, off);
        float ov1 = __shfl_xor_sync(0xffffffffu, v1, off);
        float ov2 = __shfl_xor_sync(0xffffffffu, v2, off);
        int   oi0 = __shfl_xor_sync(0xffffffffu, i0, off);
        int   oi1 = __shfl_xor_sync(0xffffffffu, i1, off);
        int   oi2 = __shfl_xor_sync(0xffffffffu, i2, off);
        ins3(ov0, oi0, v0, i0, v1, i1, v2, i2);
        ins3(ov1, oi1, v0, i0, v1, i1, v2, i2);
        ins3(ov2, oi2, v0, i0, v1, i1, v2, i2);
    }
    if (lane == 0) {
        rv[warp * 3 + 0] = v0; ri[warp * 3 + 0] = i0;
        rv[warp * 3 + 1] = v1; ri[warp * 3 + 1] = i1;
        rv[warp * 3 + 2] = v2; ri[warp * 3 + 2] = i2;
        re[warp] = ent;
    }
    __syncthreads();

    if (tid == 0) {
        float m0 = -1e30f, m1 = -1e30f, m2 = -1e30f;
        int   j0 = 0x7fffffff, j1 = 0x7fffffff, j2 = 0x7fffffff;
        for (int k = 0; k < 12; ++k) ins3(rv[k], ri[k], m0, j0, m1, j1, m2, j2);
        float entall = re[0] + re[1] + re[2] + re[3];

        float ssum = m0 + m1 + m2 + 1e-10f;
        float os = p_os[0], oa = p_oa[0], ob = p_ob[0];
        float sp_oa = (oa > 20.0f) ? oa : log1pf(expf(oa));
        float sp_ob = (ob > 20.0f) ? ob : log1pf(expf(ob));
        float sig_os = 1.0f / (1.0f + expf(-os));
        float arg = sp_oa * (sp_ob - entall);
        rb[0] = sig_os * (1.0f / (1.0f + expf(-arg)));
        rb[1] = m0 / ssum;  rb[2] = m1 / ssum;  rb[3] = m2 / ssum;
        rbi[0] = j0;        rbi[1] = j1;        rbi[2] = j2;
    }
    __syncthreads();

    const float lam = rb[0], w0 = rb[1], w1 = rb[2], w2 = rb[3];
    const float4* e0 = (const float4*)(embed + (size_t)rbi[0] * NH);
    const float4* e1 = (const float4*)(embed + (size_t)rbi[1] * NH);
    const float4* e2 = (const float4*)(embed + (size_t)rbi[2] * NH);
    const float4* er = (const float4*)(embed + (size_t)MASKID * NH);
    float4* orow = (float4*)(out + (size_t)row * NH);

#pragma unroll
    for (int j = 0; j < (NH / 4) / TPB; ++j) {      // 2 float4 per thread
        int c = tid + TPB * j;
        float4 a = e0[c], b = e1[c], cc = e2[c], r = er[c];
        float4 o;
        o.x = (1.0f - lam) * r.x + lam * (w0 * a.x + w1 * b.x + w2 * cc.x);
        o.y = (1.0f - lam) * r.y + lam * (w0 * a.y + w1 * b.y + w2 * cc.y);
        o.z = (1.0f - lam) * r.z + lam * (w0 * a.z + w1 * b.z + w2 * cc.z);
        o.w = (1.0f - lam) * r.w + lam * (w0 * a.w + w1 * b.w + w2 * cc.w);
        orow[c] = o;
    }
    __syncthreads();   // scratch safe for next mask row
}

__global__ __launch_bounds__(TPB)
void softmask_pdma(const void* __restrict__ x_t_raw,
                   const float* __restrict__ probs,
                   const float* __restrict__ embed,
                   const float* __restrict__ p_os,
                   const float* __restrict__ p_oa,
                   const float* __restrict__ p_ob,
                   float* __restrict__ out)
{
    const int tid = threadIdx.x;
    const int bid = blockIdx.x;

    const uint32_t sb = smem_u32(dsm);
    int* stoks = (int*)(dsm + OFF_TOK);
    int* mlist = (int*)(dsm + OFF_MLST);
    int* mcnt  = (int*)(dsm + OFF_MCNT);

    const int nrows = (NROWS - bid + NCTA - 1) / NCTA;   // 55 or 56

    // ---- dtype-width detection (int64 vs int32) + token preload ----
    const int* xi = (const int*)x_t_raw;
    const bool is64 = (xi[1] == 0) & (xi[3] == 0) & (xi[5] == 0) & (xi[7] == 0);
    if (tid < nrows) {
        int row = bid + tid * NCTA;
        stoks[tid] = is64 ? (int)((const long long*)x_t_raw)[row] : xi[row];
    }
    if (tid == 0) {
        *mcnt = 0;
#pragma unroll
        for (int s = 0; s < NSTG; ++s) MBAR_INIT(sb + OFF_MBAR + 8 * s, 1);
    }
    __syncthreads();

    // ---- parallel per-thread DMA: thread t owns stage t, handles rows t, t+NSTG ----
    if (tid < NSTG) {
        const uint32_t stage = sb + tid * ROWB;
        const uint32_t mb    = sb + OFF_MBAR + 8 * tid;
        int ph = 0;
#pragma unroll
        for (int r = 0; r < 2; ++r) {
            const int k = r * NSTG + tid;
            if (k < nrows) {
                const int tk = stoks[k];
                if (tk == MASKID) {
                    mlist[atomicAdd(mcnt, 1)] = k;
                } else {
                    if (r > 0) BULK_WAITG0();   // own prior S2G drained before reuse
                    MBAR_EXPECT(mb, ROWB);
                    BULK_G2S(stage, (uint64_t)(const char*)(embed + (size_t)tk * NH),
                             ROWB, mb);
                    MBAR_WAIT(mb, ph);
                    ph ^= 1;
                    BULK_S2G((uint64_t)(char*)(out + (size_t)(bid + k * NCTA) * NH),
                             stage, ROWB);
                    BULK_COMMIT();
                }
            }
        }
        BULK_WAITG0();   // all own stores complete before retire
    }
    __syncthreads();

    // ---- rare mask rows: block-cooperative ----
    const int nm = *mcnt;
    for (int m = 0; m < nm; ++m)
        heavy_row_block(bid + mlist[m] * NCTA, tid,
                        probs, embed, p_os, p_oa, p_ob, out);
}

extern "C" void kernel_launch(void* const* d_in, const int* in_sizes, int n_in,
                              void* d_out, int out_size)
{
    (void)in_sizes; (void)n_in; (void)out_size;
    const void*  x_t   = d_in[0];
    const float* probs = (const float*)d_in[1];
    const float* embed = (const float*)d_in[2];
    const float* om_s  = (const float*)d_in[3];
    const float* om_a  = (const float*)d_in[4];
    const float* om_b  = (const float*)d_in[5];
    float* out = (float*)d_out;

    cudaFuncSetAttribute(softmask_pdma,
                         cudaFuncAttributeMaxDynamicSharedMemorySize, SMEM_TOTAL);
    softmask_pdma<<<NCTA, TPB, SMEM_TOTAL>>>(x_t, probs, embed,
                                             om_s, om_a, om_b, out);
}